// round 4
// baseline (speedup 1.0000x reference)
#include <cuda_runtime.h>

// ---------------- problem constants ----------------
#define NCAND   65536
#define HID     1024
#define BOARD2  361
#define CPOL    256
#define KCAND   64

// ---------------- GEMM tiling (legacy mma.sync tf32 path) ----------------
#define BM 128
#define BN 128
#define BK 32
#define STAGES 3
#define THREADS 128
#define SA_STRIDE 36     // %32==4 -> conflict-free A frag loads (row varies over lanes)
#define SB_STRIDE 136    // %32==8 -> conflict-free B frag loads (k row varies over lanes)
#define SA_BUF (BM*SA_STRIDE)            // 4608 floats
#define SB_BUF (BK*SB_STRIDE)            // 4352 floats
#define STAGE_FLOATS (SA_BUF + SB_BUF)   // 8960
#define SMEM_BYTES (STAGES*STAGE_FLOATS*4)  // 107520

// ---------------- device scratch ----------------
__device__ float g_pfmT[BOARD2*CPOL];
__device__ float g_pool[CPOL];
__device__ float g_P1[BOARD2*HID];
__device__ float g_P2[BOARD2*HID];
__device__ float g_bias1[HID];
__device__ int   g_go[NCAND];
__device__ int   g_to[NCAND];
__device__ float g_candt[NCAND*KCAND];      // tf32-rounded cand feats  [m][64]
__device__ float g_W1ct[KCAND*HID];         // tf32-rounded W1[768:832] [k][n]
__device__ float g_W2t[HID*HID];            // tf32-rounded W2          [k][n]
__device__ float g_h1[(size_t)NCAND*HID];   // layer-1 activations (tf32-rounded)

// ---------------- helpers ----------------
__device__ __forceinline__ float tf32r(float x) {
    unsigned u;
    asm("cvt.rna.tf32.f32 %0, %1;" : "=r"(u) : "f"(x));
    return __uint_as_float(u);
}

__device__ __forceinline__ void cpa16(const float* smem_dst, const float* gmem_src) {
    unsigned sa;
    asm("{ .reg .u64 t; cvta.to.shared.u64 t, %1; cvt.u32.u64 %0, t; }"
        : "=r"(sa) : "l"(smem_dst));
    asm volatile("cp.async.cg.shared.global [%0], [%1], 16;" :: "r"(sa), "l"(gmem_src));
}
#define CP_COMMIT() asm volatile("cp.async.commit_group;")
template<int N>
__device__ __forceinline__ void cp_wait() {
    asm volatile("cp.async.wait_group %0;" :: "n"(N));
}

__device__ __forceinline__ void mma8(float* c, const float* a, const float* b) {
    const unsigned* A = reinterpret_cast<const unsigned*>(a);
    const unsigned* B = reinterpret_cast<const unsigned*>(b);
    asm volatile(
        "mma.sync.aligned.m16n8k8.row.col.f32.tf32.tf32.f32 "
        "{%0,%1,%2,%3}, {%4,%5,%6,%7}, {%8,%9}, {%0,%1,%2,%3};"
        : "+f"(c[0]), "+f"(c[1]), "+f"(c[2]), "+f"(c[3])
        : "r"(A[0]), "r"(A[1]), "r"(A[2]), "r"(A[3]), "r"(B[0]), "r"(B[1]));
}

// ---------------- prep kernels ----------------
__global__ void k_prep(const float* __restrict__ pfm) {
    int c = blockIdx.x;
    float s = 0.f;
    for (int p = threadIdx.x; p < BOARD2; p += 128) {
        float v = pfm[c*BOARD2 + p];
        g_pfmT[p*CPOL + c] = v;
        s += v;
    }
    __shared__ float red[128];
    red[threadIdx.x] = s; __syncthreads();
    for (int o = 64; o > 0; o >>= 1) {
        if (threadIdx.x < o) red[threadIdx.x] += red[threadIdx.x + o];
        __syncthreads();
    }
    if (threadIdx.x == 0) g_pool[c] = red[0] / 361.0f;
}

__global__ void k_pos(const float* __restrict__ cand) {
    int i = blockIdx.x*blockDim.x + threadIdx.x;
    if (i >= NCAND) return;
    const float* f = cand + (size_t)i*KCAND;
    int gr = min(max((int)(f[5]*18.f), 0), 18);
    int gc = min(max((int)(f[6]*18.f), 0), 18);
    int tr = min(max((int)(f[7]*18.f), 0), 18);
    int tc = min(max((int)(f[8]*18.f), 0), 18);
    g_go[i] = gr*19 + gc;
    g_to[i] = tr*19 + tc;
}

// P1 = pfmT @ W1[0:256],  P2 = pfmT @ W1[256:512]   (fp32, exact)
__global__ void k_pw(const float* __restrict__ W1) {
    __shared__ float sT[16*CPOL];
    int p0 = blockIdx.x*16;
    int o  = blockIdx.y*128 + threadIdx.x;
    for (int idx = threadIdx.x; idx < 16*CPOL; idx += 128) {
        int p = idx >> 8, c = idx & 255;
        sT[idx] = (p0 + p < BOARD2) ? g_pfmT[(p0+p)*CPOL + c] : 0.f;
    }
    __syncthreads();
    float a1[16], a2[16];
    #pragma unroll
    for (int p = 0; p < 16; p++) { a1[p] = 0.f; a2[p] = 0.f; }
    for (int c = 0; c < CPOL; c++) {
        float w1 = W1[(size_t)c*HID + o];
        float w2 = W1[(size_t)(c+256)*HID + o];
        #pragma unroll
        for (int p = 0; p < 16; p++) {
            float t = sT[p*CPOL + c];
            a1[p] += t*w1; a2[p] += t*w2;
        }
    }
    for (int p = 0; p < 16; p++)
        if (p0 + p < BOARD2) {
            g_P1[(p0+p)*HID + o] = a1[p];
            g_P2[(p0+p)*HID + o] = a2[p];
        }
}

// bias1 = b1 + pool @ W1[512:768]    (k-parallel: 8 k-groups x 32 outputs per block)
__global__ void k_bias1(const float* __restrict__ W1, const float* __restrict__ b1) {
    __shared__ float red[8][32];
    int o  = blockIdx.x*32 + (threadIdx.x & 31);
    int kg = threadIdx.x >> 5;               // 0..7
    float s = 0.f;
    #pragma unroll 8
    for (int c = kg*32; c < kg*32 + 32; c++)
        s += g_pool[c] * W1[(size_t)(512+c)*HID + o];
    red[kg][threadIdx.x & 31] = s;
    __syncthreads();
    if (kg == 0) {
        float t = b1[o];
        #pragma unroll
        for (int j = 0; j < 8; j++) t += red[j][threadIdx.x & 31];
        g_bias1[o] = t;
    }
}

__global__ void k_round_cand(const float* __restrict__ cand) {
    int i = blockIdx.x*blockDim.x + threadIdx.x;
    if (i < NCAND*KCAND) g_candt[i] = tf32r(cand[i]);
}
__global__ void k_round_w(const float* __restrict__ W1, const float* __restrict__ W2) {
    int i = blockIdx.x*blockDim.x + threadIdx.x;
    if (i < HID*HID) g_W2t[i] = tf32r(W2[i]);
    if (i < KCAND*HID) g_W1ct[i] = tf32r(W1[(size_t)768*HID + i]);
}
__global__ void k_out_init(float* __restrict__ out, const float* __restrict__ b3) {
    int i = blockIdx.x*blockDim.x + threadIdx.x;
    if (i < NCAND) out[i] = b3[0];
}

// ---------------- main GEMM: 128x128 CTA, 4 warps of 64x64, 3-stage cp.async ----------------
// EPI==0: h1 = relu(cand@W1c + P1[go] + P2[to] + bias1)   (K=64)
// EPI==1: out += sum_n relu(h1@W2 + b2)[:,n] * W3[n]      (K=1024)
template<int EPI>
__global__ __launch_bounds__(THREADS, 2) void k_gemm(
    const float* __restrict__ b2, const float* __restrict__ W3, float* __restrict__ outp)
{
    extern __shared__ float sm[];

    constexpr int lda = EPI ? HID : KCAND;
    constexpr int nck = EPI ? HID/BK : KCAND/BK;
    const float* __restrict__ Ag = EPI ? g_h1  : g_candt;
    const float* __restrict__ Bg = EPI ? g_W2t : g_W1ct;

    const int tid = threadIdx.x, lane = tid & 31, wid = tid >> 5;
    const int wm = wid >> 1, wn = wid & 1;       // 2x2 warp grid
    const int g = lane >> 2, t4 = lane & 3;
    const int col0 = blockIdx.x * BN;            // x fastest -> A rows reused in L2
    const int row0 = blockIdx.y * BM;

    auto issue = [&](int ck, int s) {
        float* sA = sm + s*STAGE_FLOATS;
        float* sB = sA + SA_BUF;
        const int k0 = ck * BK;
        #pragma unroll
        for (int i = 0; i < 8; i++) {            // A: 128 rows x 32 floats
            int idx = tid + i*THREADS;
            int r = idx >> 3, c4 = idx & 7;
            cpa16(sA + r*SA_STRIDE + c4*4,
                  Ag + (size_t)(row0 + r)*lda + k0 + c4*4);
        }
        #pragma unroll
        for (int i = 0; i < 8; i++) {            // B: 32 rows x 128 floats
            int idx = tid + i*THREADS;
            int k = idx >> 5, n4 = idx & 31;
            cpa16(sB + k*SB_STRIDE + n4*4,
                  Bg + (size_t)(k0 + k)*HID + col0 + n4*4);
        }
        CP_COMMIT();
    };

    float acc[4][8][4];
    #pragma unroll
    for (int mt = 0; mt < 4; mt++)
        #pragma unroll
        for (int nt = 0; nt < 8; nt++)
            #pragma unroll
            for (int q = 0; q < 4; q++) acc[mt][nt][q] = 0.f;

    #pragma unroll
    for (int s = 0; s < STAGES-1 && s < nck; s++) issue(s, s);

    for (int ck = 0; ck < nck; ck++) {
        const int buf = ck % STAGES;
        const int rem = nck - 1 - ck;            // chunks still to consume after this
        if (ck + STAGES - 1 < nck) issue(ck + STAGES - 1, (ck + STAGES - 1) % STAGES);
        if (rem >= 2)      cp_wait<2>();
        else if (rem == 1) cp_wait<1>();
        else               cp_wait<0>();
        __syncthreads();

        const float* sA = sm + buf*STAGE_FLOATS;
        const float* sB = sA + SA_BUF;
        const float* pA = sA + (wm*64 + g)*SA_STRIDE + t4;
        const float* pB = sB + t4*SB_STRIDE + wn*64 + g;

        #pragma unroll
        for (int ks = 0; ks < 4; ks++) {
            const int k = ks*8;
            float a[4][4], b[8][2];
            #pragma unroll
            for (int mt = 0; mt < 4; mt++) {
                const float* p = pA + mt*16*SA_STRIDE + k;
                a[mt][0] = p[0];
                a[mt][1] = p[8*SA_STRIDE];
                a[mt][2] = p[4];
                a[mt][3] = p[8*SA_STRIDE + 4];
            }
            #pragma unroll
            for (int nt = 0; nt < 8; nt++) {
                const float* p = pB + k*SB_STRIDE + nt*8;
                b[nt][0] = p[0];
                b[nt][1] = p[4*SB_STRIDE];
            }
            #pragma unroll
            for (int mt = 0; mt < 4; mt++)
                #pragma unroll
                for (int nt = 0; nt < 8; nt++)
                    mma8(acc[mt][nt], a[mt], b[nt]);
        }
        __syncthreads();
    }

    // -------- epilogue --------
    if (EPI == 0) {
        #pragma unroll
        for (int mt = 0; mt < 4; mt++) {
            const int r1 = row0 + wm*64 + mt*16 + g;
            const int r2 = r1 + 8;
            const int go1 = g_go[r1], to1 = g_to[r1];
            const int go2 = g_go[r2], to2 = g_to[r2];
            const float* P1a = g_P1 + (size_t)go1*HID;
            const float* P2a = g_P2 + (size_t)to1*HID;
            const float* P1b = g_P1 + (size_t)go2*HID;
            const float* P2b = g_P2 + (size_t)to2*HID;
            #pragma unroll
            for (int nt = 0; nt < 8; nt++) {
                const int c = col0 + wn*64 + nt*8 + 2*t4;
                float2 bs  = *(const float2*)&g_bias1[c];
                float2 p1a = *(const float2*)&P1a[c];
                float2 p2a = *(const float2*)&P2a[c];
                float2 p1b = *(const float2*)&P1b[c];
                float2 p2b = *(const float2*)&P2b[c];
                float2 o1, o2;
                o1.x = tf32r(fmaxf(acc[mt][nt][0] + p1a.x + p2a.x + bs.x, 0.f));
                o1.y = tf32r(fmaxf(acc[mt][nt][1] + p1a.y + p2a.y + bs.y, 0.f));
                o2.x = tf32r(fmaxf(acc[mt][nt][2] + p1b.x + p2b.x + bs.x, 0.f));
                o2.y = tf32r(fmaxf(acc[mt][nt][3] + p1b.y + p2b.y + bs.y, 0.f));
                *(float2*)&g_h1[(size_t)r1*HID + c] = o1;
                *(float2*)&g_h1[(size_t)r2*HID + c] = o2;
            }
        }
    } else {
        float rs[4][2];
        #pragma unroll
        for (int mt = 0; mt < 4; mt++) { rs[mt][0] = 0.f; rs[mt][1] = 0.f; }
        #pragma unroll
        for (int nt = 0; nt < 8; nt++) {
            const int c = col0 + wn*64 + nt*8 + 2*t4;
            float2 bb = *(const float2*)&b2[c];
            float2 ww = *(const float2*)&W3[c];
            #pragma unroll
            for (int mt = 0; mt < 4; mt++) {
                rs[mt][0] += fmaxf(acc[mt][nt][0] + bb.x, 0.f)*ww.x
                           + fmaxf(acc[mt][nt][1] + bb.y, 0.f)*ww.y;
                rs[mt][1] += fmaxf(acc[mt][nt][2] + bb.x, 0.f)*ww.x
                           + fmaxf(acc[mt][nt][3] + bb.y, 0.f)*ww.y;
            }
        }
        #pragma unroll
        for (int mt = 0; mt < 4; mt++)
            #pragma unroll
            for (int j = 0; j < 2; j++) {
                float v = rs[mt][j];
                v += __shfl_xor_sync(0xffffffffu, v, 1);
                v += __shfl_xor_sync(0xffffffffu, v, 2);
                if (t4 == 0)
                    atomicAdd(outp + row0 + wm*64 + mt*16 + g + 8*j, v);
            }
    }
}

// ---------------- launch ----------------
extern "C" void kernel_launch(void* const* d_in, const int* in_sizes, int n_in,
                              void* d_out, int out_size)
{
    const float* pfm  = (const float*)d_in[0];
    const float* cand = (const float*)d_in[1];
    const float* W1   = (const float*)d_in[2];
    const float* b1   = (const float*)d_in[3];
    const float* W2   = (const float*)d_in[4];
    const float* b2   = (const float*)d_in[5];
    const float* W3   = (const float*)d_in[6];
    const float* b3   = (const float*)d_in[7];
    float* out = (float*)d_out;

    cudaFuncSetAttribute(k_gemm<0>, cudaFuncAttributeMaxDynamicSharedMemorySize, SMEM_BYTES);
    cudaFuncSetAttribute(k_gemm<1>, cudaFuncAttributeMaxDynamicSharedMemorySize, SMEM_BYTES);

    k_prep<<<CPOL, 128>>>(pfm);
    k_pos<<<NCAND/256, 256>>>(cand);
    k_pw<<<dim3(23, 8), 128>>>(W1);
    k_bias1<<<HID/32, 256>>>(W1, b1);
    k_round_cand<<<(NCAND*KCAND)/256, 256>>>(cand);
    k_round_w<<<(HID*HID)/256, 256>>>(W1, W2);
    k_out_init<<<NCAND/256, 256>>>(out, b3);

    dim3 grid(HID/BN, NCAND/BM);   // (8, 512): col-block fastest
    k_gemm<0><<<grid, THREADS, SMEM_BYTES>>>(nullptr, nullptr, nullptr);
    k_gemm<1><<<grid, THREADS, SMEM_BYTES>>>(b2, W3, out);
}

// round 5
// speedup vs baseline: 1.4926x; 1.4926x over previous
#include <cuda_runtime.h>
#include <cuda_fp16.h>

// ---------------- problem constants ----------------
#define NCAND   65536
#define HID     1024
#define BOARD2  361
#define CPOL    256
#define KCAND   64

// ---------------- GEMM tiling (fp16 mma.sync m16n8k16) ----------------
#define BM 128
#define BN 128
#define BK 32            // two k16 mma steps per chunk
#define STAGES 3
#define THREADS 128
#define SA_STRIDE 56     // halves; 112B row: 16B-aligned, conflict-free frag loads
#define SB_STRIDE 56
#define SA_BUF (BM*SA_STRIDE)            // 7168 halves
#define SB_BUF (BN*SB_STRIDE)            // 7168 halves
#define STAGE_HALVES (SA_BUF + SB_BUF)   // 14336
#define SMEM_BYTES (STAGES*STAGE_HALVES*2)  // 86016

// ---------------- device scratch ----------------
__device__ float g_pfmT[BOARD2*CPOL];
__device__ float g_pool[CPOL];
__device__ float g_P1[BOARD2*HID];
__device__ float g_P2[BOARD2*HID];
__device__ float g_bias1[HID];
__device__ int   g_go[NCAND];
__device__ int   g_to[NCAND];
__device__ __align__(16) __half g_candh[NCAND*KCAND];     // fp16 cand feats [m][64]
__device__ __align__(16) __half g_W1ch[HID*KCAND];        // fp16 W1[768:832]^T [n][k]
__device__ __align__(16) __half g_W2h[HID*HID];           // fp16 W2^T          [n][k]
__device__ __align__(16) __half g_h1[(size_t)NCAND*HID];  // layer-1 activations fp16

// ---------------- helpers ----------------
__device__ __forceinline__ void cpa16(const void* smem_dst, const void* gmem_src) {
    unsigned sa;
    asm("{ .reg .u64 t; cvta.to.shared.u64 t, %1; cvt.u32.u64 %0, t; }"
        : "=r"(sa) : "l"(smem_dst));
    asm volatile("cp.async.cg.shared.global [%0], [%1], 16;" :: "r"(sa), "l"(gmem_src));
}
#define CP_COMMIT() asm volatile("cp.async.commit_group;")
template<int N>
__device__ __forceinline__ void cp_wait() {
    asm volatile("cp.async.wait_group %0;" :: "n"(N));
}

__device__ __forceinline__ void mma16(float* c, const unsigned* a, const unsigned* b) {
    asm volatile(
        "mma.sync.aligned.m16n8k16.row.col.f32.f16.f16.f32 "
        "{%0,%1,%2,%3}, {%4,%5,%6,%7}, {%8,%9}, {%0,%1,%2,%3};"
        : "+f"(c[0]), "+f"(c[1]), "+f"(c[2]), "+f"(c[3])
        : "r"(a[0]), "r"(a[1]), "r"(a[2]), "r"(a[3]), "r"(b[0]), "r"(b[1]));
}

// ---------------- prep kernels ----------------
__global__ void k_prep(const float* __restrict__ pfm) {
    int c = blockIdx.x;
    float s = 0.f;
    for (int p = threadIdx.x; p < BOARD2; p += 128) {
        float v = pfm[c*BOARD2 + p];
        g_pfmT[p*CPOL + c] = v;
        s += v;
    }
    __shared__ float red[128];
    red[threadIdx.x] = s; __syncthreads();
    for (int o = 64; o > 0; o >>= 1) {
        if (threadIdx.x < o) red[threadIdx.x] += red[threadIdx.x + o];
        __syncthreads();
    }
    if (threadIdx.x == 0) g_pool[c] = red[0] / 361.0f;
}

__global__ void k_pos(const float* __restrict__ cand) {
    int i = blockIdx.x*blockDim.x + threadIdx.x;
    if (i >= NCAND) return;
    const float* f = cand + (size_t)i*KCAND;
    int gr = min(max((int)(f[5]*18.f), 0), 18);
    int gc = min(max((int)(f[6]*18.f), 0), 18);
    int tr = min(max((int)(f[7]*18.f), 0), 18);
    int tc = min(max((int)(f[8]*18.f), 0), 18);
    g_go[i] = gr*19 + gc;
    g_to[i] = tr*19 + tc;
}

// P1 = pfmT @ W1[0:256],  P2 = pfmT @ W1[256:512]   (fp32, exact)
__global__ void k_pw(const float* __restrict__ W1) {
    __shared__ float sT[16*CPOL];
    int p0 = blockIdx.x*16;
    int o  = blockIdx.y*128 + threadIdx.x;
    for (int idx = threadIdx.x; idx < 16*CPOL; idx += 128) {
        int p = idx >> 8, c = idx & 255;
        sT[idx] = (p0 + p < BOARD2) ? g_pfmT[(p0+p)*CPOL + c] : 0.f;
    }
    __syncthreads();
    float a1[16], a2[16];
    #pragma unroll
    for (int p = 0; p < 16; p++) { a1[p] = 0.f; a2[p] = 0.f; }
    for (int c = 0; c < CPOL; c++) {
        float w1 = W1[(size_t)c*HID + o];
        float w2 = W1[(size_t)(c+256)*HID + o];
        #pragma unroll
        for (int p = 0; p < 16; p++) {
            float t = sT[p*CPOL + c];
            a1[p] += t*w1; a2[p] += t*w2;
        }
    }
    for (int p = 0; p < 16; p++)
        if (p0 + p < BOARD2) {
            g_P1[(p0+p)*HID + o] = a1[p];
            g_P2[(p0+p)*HID + o] = a2[p];
        }
}

// bias1 = b1 + pool @ W1[512:768]    (k-parallel)
__global__ void k_bias1(const float* __restrict__ W1, const float* __restrict__ b1) {
    __shared__ float red[8][32];
    int o  = blockIdx.x*32 + (threadIdx.x & 31);
    int kg = threadIdx.x >> 5;
    float s = 0.f;
    #pragma unroll 8
    for (int c = kg*32; c < kg*32 + 32; c++)
        s += g_pool[c] * W1[(size_t)(512+c)*HID + o];
    red[kg][threadIdx.x & 31] = s;
    __syncthreads();
    if (kg == 0) {
        float t = b1[o];
        #pragma unroll
        for (int j = 0; j < 8; j++) t += red[j][threadIdx.x & 31];
        g_bias1[o] = t;
    }
}

__global__ void k_cand_h(const float* __restrict__ cand) {
    int i = blockIdx.x*blockDim.x + threadIdx.x;
    if (i < NCAND*KCAND) g_candh[i] = __float2half_rn(cand[i]);
}

// W2^T -> fp16 [n][k]
__global__ void k_w2h(const float* __restrict__ W2) {
    __shared__ float t[32][33];
    int bx = blockIdx.x*32, by = blockIdx.y*32;   // bx: n base, by: k base
    int x = threadIdx.x, y = threadIdx.y;
    for (int i = y; i < 32; i += 8)
        t[i][x] = W2[(size_t)(by+i)*HID + bx + x];
    __syncthreads();
    for (int i = y; i < 32; i += 8)
        g_W2h[(size_t)(bx+i)*HID + by + x] = __float2half_rn(t[x][i]);
}

// W1c^T -> fp16 [n][64]
__global__ void k_w1ch(const float* __restrict__ W1) {
    int k = blockIdx.x;                    // 0..63
    int n = blockIdx.y*256 + threadIdx.x;  // 0..1023
    g_W1ch[(size_t)n*KCAND + k] = __float2half_rn(W1[(size_t)(768+k)*HID + n]);
}

__global__ void k_out_init(float* __restrict__ out, const float* __restrict__ b3) {
    int i = blockIdx.x*blockDim.x + threadIdx.x;
    if (i < NCAND) out[i] = b3[0];
}

// ---------------- main GEMM: 128x128 CTA, 4 warps of 64x64, fp16 HMMA ----------------
// EPI==0: h1 = relu(cand@W1c + P1[go] + P2[to] + bias1)   (K=64)
// EPI==1: out += sum_n relu(h1@W2 + b2)[:,n] * W3[n]      (K=1024)
template<int EPI>
__global__ __launch_bounds__(THREADS, 2) void k_gemm(
    const float* __restrict__ b2, const float* __restrict__ W3, float* __restrict__ outp)
{
    extern __shared__ __align__(16) __half sm[];

    constexpr int lda = EPI ? HID : KCAND;   // A row length (halves)
    constexpr int ldb = EPI ? HID : KCAND;   // B ([n][k]) row length (halves)
    constexpr int nck = EPI ? HID/BK : KCAND/BK;
    const __half* __restrict__ Ag = EPI ? g_h1  : g_candh;
    const __half* __restrict__ Bg = EPI ? g_W2h : g_W1ch;

    const int tid = threadIdx.x, lane = tid & 31, wid = tid >> 5;
    const int wm = wid >> 1, wn = wid & 1;       // 2x2 warp grid, 64x64 tiles
    const int g = lane >> 2, t4 = lane & 3;
    const int col0 = blockIdx.x * BN;            // x fastest -> A rows reused in L2
    const int row0 = blockIdx.y * BM;

    auto issue = [&](int ck, int s) {
        __half* sA = sm + s*STAGE_HALVES;
        __half* sB = sA + SA_BUF;
        const int k0 = ck * BK;
        #pragma unroll
        for (int i = 0; i < 4; i++) {            // A: 128 rows x 32 halves (4x16B/row)
            int idx = tid + i*THREADS;
            int r = idx >> 2, c4 = idx & 3;
            cpa16(sA + r*SA_STRIDE + c4*8,
                  Ag + (size_t)(row0 + r)*lda + k0 + c4*8);
        }
        #pragma unroll
        for (int i = 0; i < 4; i++) {            // B: 128 n-rows x 32 halves
            int idx = tid + i*THREADS;
            int r = idx >> 2, c4 = idx & 3;
            cpa16(sB + r*SB_STRIDE + c4*8,
                  Bg + (size_t)(col0 + r)*ldb + k0 + c4*8);
        }
        CP_COMMIT();
    };

    float acc[4][8][4];
    #pragma unroll
    for (int mt = 0; mt < 4; mt++)
        #pragma unroll
        for (int nt = 0; nt < 8; nt++)
            #pragma unroll
            for (int q = 0; q < 4; q++) acc[mt][nt][q] = 0.f;

    #pragma unroll
    for (int s = 0; s < STAGES-1 && s < nck; s++) issue(s, s);

    for (int ck = 0; ck < nck; ck++) {
        const int buf = ck % STAGES;
        const int rem = nck - 1 - ck;
        if (ck + STAGES - 1 < nck) issue(ck + STAGES - 1, (ck + STAGES - 1) % STAGES);
        if (rem >= 2)      cp_wait<2>();
        else if (rem == 1) cp_wait<1>();
        else               cp_wait<0>();
        __syncthreads();

        const __half* sA = sm + buf*STAGE_HALVES;
        const __half* sB = sA + SA_BUF;
        const __half* pA = sA + (wm*64 + g)*SA_STRIDE + 2*t4;
        const __half* pB = sB + (wn*64 + g)*SB_STRIDE + 2*t4;

        #pragma unroll
        for (int ks = 0; ks < 2; ks++) {         // two k16 steps
            const int kofs = ks*16;
            unsigned a[4][4], b[8][2];
            #pragma unroll
            for (int mt = 0; mt < 4; mt++) {
                const __half* p = pA + mt*16*SA_STRIDE + kofs;
                a[mt][0] = *(const unsigned*)(p);
                a[mt][1] = *(const unsigned*)(p + 8*SA_STRIDE);
                a[mt][2] = *(const unsigned*)(p + 8);
                a[mt][3] = *(const unsigned*)(p + 8*SA_STRIDE + 8);
            }
            #pragma unroll
            for (int nt = 0; nt < 8; nt++) {
                const __half* p = pB + nt*8*SB_STRIDE + kofs;
                b[nt][0] = *(const unsigned*)(p);
                b[nt][1] = *(const unsigned*)(p + 8);
            }
            #pragma unroll
            for (int mt = 0; mt < 4; mt++)
                #pragma unroll
                for (int nt = 0; nt < 8; nt++)
                    mma16(acc[mt][nt], a[mt], b[nt]);
        }
        __syncthreads();
    }

    // -------- epilogue (C frag: c0,c1 = row g cols 2t4,2t4+1; c2,c3 = row g+8) ----
    if (EPI == 0) {
        #pragma unroll
        for (int mt = 0; mt < 4; mt++) {
            const int r1 = row0 + wm*64 + mt*16 + g;
            const int r2 = r1 + 8;
            const int go1 = g_go[r1], to1 = g_to[r1];
            const int go2 = g_go[r2], to2 = g_to[r2];
            const float* P1a = g_P1 + (size_t)go1*HID;
            const float* P2a = g_P2 + (size_t)to1*HID;
            const float* P1b = g_P1 + (size_t)go2*HID;
            const float* P2b = g_P2 + (size_t)to2*HID;
            #pragma unroll
            for (int nt = 0; nt < 8; nt++) {
                const int c = col0 + wn*64 + nt*8 + 2*t4;
                float2 bs  = *(const float2*)&g_bias1[c];
                float2 p1a = *(const float2*)&P1a[c];
                float2 p2a = *(const float2*)&P2a[c];
                float2 p1b = *(const float2*)&P1b[c];
                float2 p2b = *(const float2*)&P2b[c];
                float v0 = fmaxf(acc[mt][nt][0] + p1a.x + p2a.x + bs.x, 0.f);
                float v1 = fmaxf(acc[mt][nt][1] + p1a.y + p2a.y + bs.y, 0.f);
                float v2 = fmaxf(acc[mt][nt][2] + p1b.x + p2b.x + bs.x, 0.f);
                float v3 = fmaxf(acc[mt][nt][3] + p1b.y + p2b.y + bs.y, 0.f);
                *(__half2*)&g_h1[(size_t)r1*HID + c] = __floats2half2_rn(v0, v1);
                *(__half2*)&g_h1[(size_t)r2*HID + c] = __floats2half2_rn(v2, v3);
            }
        }
    } else {
        float rs[4][2];
        #pragma unroll
        for (int mt = 0; mt < 4; mt++) { rs[mt][0] = 0.f; rs[mt][1] = 0.f; }
        #pragma unroll
        for (int nt = 0; nt < 8; nt++) {
            const int c = col0 + wn*64 + nt*8 + 2*t4;
            float2 bb = *(const float2*)&b2[c];
            float2 ww = *(const float2*)&W3[c];
            #pragma unroll
            for (int mt = 0; mt < 4; mt++) {
                rs[mt][0] += fmaxf(acc[mt][nt][0] + bb.x, 0.f)*ww.x
                           + fmaxf(acc[mt][nt][1] + bb.y, 0.f)*ww.y;
                rs[mt][1] += fmaxf(acc[mt][nt][2] + bb.x, 0.f)*ww.x
                           + fmaxf(acc[mt][nt][3] + bb.y, 0.f)*ww.y;
            }
        }
        #pragma unroll
        for (int mt = 0; mt < 4; mt++)
            #pragma unroll
            for (int j = 0; j < 2; j++) {
                float v = rs[mt][j];
                v += __shfl_xor_sync(0xffffffffu, v, 1);
                v += __shfl_xor_sync(0xffffffffu, v, 2);
                if (t4 == 0)
                    atomicAdd(outp + row0 + wm*64 + mt*16 + g + 8*j, v);
            }
    }
}

// ---------------- launch ----------------
extern "C" void kernel_launch(void* const* d_in, const int* in_sizes, int n_in,
                              void* d_out, int out_size)
{
    const float* pfm  = (const float*)d_in[0];
    const float* cand = (const float*)d_in[1];
    const float* W1   = (const float*)d_in[2];
    const float* b1   = (const float*)d_in[3];
    const float* W2   = (const float*)d_in[4];
    const float* b2   = (const float*)d_in[5];
    const float* W3   = (const float*)d_in[6];
    const float* b3   = (const float*)d_in[7];
    float* out = (float*)d_out;

    cudaFuncSetAttribute(k_gemm<0>, cudaFuncAttributeMaxDynamicSharedMemorySize, SMEM_BYTES);
    cudaFuncSetAttribute(k_gemm<1>, cudaFuncAttributeMaxDynamicSharedMemorySize, SMEM_BYTES);

    k_prep<<<CPOL, 128>>>(pfm);
    k_pos<<<NCAND/256, 256>>>(cand);
    k_pw<<<dim3(23, 8), 128>>>(W1);
    k_bias1<<<HID/32, 256>>>(W1, b1);
    k_cand_h<<<(NCAND*KCAND)/256, 256>>>(cand);
    k_w2h<<<dim3(HID/32, HID/32), dim3(32, 8)>>>(W2);
    k_w1ch<<<dim3(KCAND, HID/256), 256>>>(W1);
    k_out_init<<<NCAND/256, 256>>>(out, b3);

    dim3 grid(HID/BN, NCAND/BM);   // (8, 512): col-block fastest
    k_gemm<0><<<grid, THREADS, SMEM_BYTES>>>(nullptr, nullptr, nullptr);
    k_gemm<1><<<grid, THREADS, SMEM_BYTES>>>(b2, W3, out);
}

// round 6
// speedup vs baseline: 1.5043x; 1.0079x over previous
#include <cuda_runtime.h>
#include <cuda_fp16.h>

// ---------------- problem constants ----------------
#define NCAND   65536
#define HID     1024
#define BOARD2  361
#define CPOL    256
#define KCAND   64

// ---------------- GEMM tiling (fp16 mma.sync m16n8k16 + ldmatrix) ----------------
#define BM 128
#define BN 128
#define BK 32            // two k16 mma steps per chunk
#define STAGES 4
#define THREADS 128
#define SA_STRIDE 40     // halves; 80B row: 16B-aligned, 80/16 odd -> LDSM conflict-free
#define SB_STRIDE 40
#define SA_BUF (BM*SA_STRIDE)            // 5120 halves
#define SB_BUF (BN*SB_STRIDE)            // 5120 halves
#define STAGE_HALVES (SA_BUF + SB_BUF)   // 10240
#define SMEM_BYTES (STAGES*STAGE_HALVES*2)  // 81920

// ---------------- device scratch ----------------
__device__ float g_pfmT[BOARD2*CPOL];
__device__ float g_pool[CPOL];
__device__ float g_P1[BOARD2*HID];
__device__ float g_P2[BOARD2*HID];
__device__ float g_bias1[HID];
__device__ int   g_go[NCAND];
__device__ int   g_to[NCAND];
__device__ __align__(16) __half g_candh[NCAND*KCAND];     // fp16 cand feats [m][64]
__device__ __align__(16) __half g_W1ch[HID*KCAND];        // fp16 W1[768:832]^T [n][k]
__device__ __align__(16) __half g_W2h[HID*HID];           // fp16 W2^T          [n][k]
__device__ __align__(16) __half g_h1[(size_t)NCAND*HID];  // layer-1 activations fp16

// ---------------- helpers ----------------
__device__ __forceinline__ void cpa16(const void* smem_dst, const void* gmem_src) {
    unsigned sa;
    asm("{ .reg .u64 t; cvta.to.shared.u64 t, %1; cvt.u32.u64 %0, t; }"
        : "=r"(sa) : "l"(smem_dst));
    asm volatile("cp.async.cg.shared.global [%0], [%1], 16;" :: "r"(sa), "l"(gmem_src));
}
#define CP_COMMIT() asm volatile("cp.async.commit_group;")
template<int N>
__device__ __forceinline__ void cp_wait() {
    asm volatile("cp.async.wait_group %0;" :: "n"(N));
}

__device__ __forceinline__ void ldsm4(unsigned& r0, unsigned& r1, unsigned& r2, unsigned& r3,
                                      const __half* p) {
    unsigned sa;
    asm("{ .reg .u64 t; cvta.to.shared.u64 t, %1; cvt.u32.u64 %0, t; }"
        : "=r"(sa) : "l"(p));
    asm volatile("ldmatrix.sync.aligned.m8n8.x4.shared.b16 {%0,%1,%2,%3}, [%4];"
        : "=r"(r0), "=r"(r1), "=r"(r2), "=r"(r3) : "r"(sa));
}

__device__ __forceinline__ void mma16(float* c, const unsigned* a, const unsigned* b) {
    asm volatile(
        "mma.sync.aligned.m16n8k16.row.col.f32.f16.f16.f32 "
        "{%0,%1,%2,%3}, {%4,%5,%6,%7}, {%8,%9}, {%0,%1,%2,%3};"
        : "+f"(c[0]), "+f"(c[1]), "+f"(c[2]), "+f"(c[3])
        : "r"(a[0]), "r"(a[1]), "r"(a[2]), "r"(a[3]), "r"(b[0]), "r"(b[1]));
}

// ---------------- prep kernels ----------------
__global__ void k_prep(const float* __restrict__ pfm) {
    int c = blockIdx.x;
    float s = 0.f;
    for (int p = threadIdx.x; p < BOARD2; p += 128) {
        float v = pfm[c*BOARD2 + p];
        g_pfmT[p*CPOL + c] = v;
        s += v;
    }
    __shared__ float red[128];
    red[threadIdx.x] = s; __syncthreads();
    for (int o = 64; o > 0; o >>= 1) {
        if (threadIdx.x < o) red[threadIdx.x] += red[threadIdx.x + o];
        __syncthreads();
    }
    if (threadIdx.x == 0) g_pool[c] = red[0] / 361.0f;
}

__global__ void k_pos(const float* __restrict__ cand) {
    int i = blockIdx.x*blockDim.x + threadIdx.x;
    if (i >= NCAND) return;
    const float* f = cand + (size_t)i*KCAND;
    int gr = min(max((int)(f[5]*18.f), 0), 18);
    int gc = min(max((int)(f[6]*18.f), 0), 18);
    int tr = min(max((int)(f[7]*18.f), 0), 18);
    int tc = min(max((int)(f[8]*18.f), 0), 18);
    g_go[i] = gr*19 + gc;
    g_to[i] = tr*19 + tc;
}

// P1 = pfmT @ W1[0:256],  P2 = pfmT @ W1[256:512]   (fp32, exact)
__global__ void k_pw(const float* __restrict__ W1) {
    __shared__ float sT[16*CPOL];
    int p0 = blockIdx.x*16;
    int o  = blockIdx.y*128 + threadIdx.x;
    for (int idx = threadIdx.x; idx < 16*CPOL; idx += 128) {
        int p = idx >> 8, c = idx & 255;
        sT[idx] = (p0 + p < BOARD2) ? g_pfmT[(p0+p)*CPOL + c] : 0.f;
    }
    __syncthreads();
    float a1[16], a2[16];
    #pragma unroll
    for (int p = 0; p < 16; p++) { a1[p] = 0.f; a2[p] = 0.f; }
    for (int c = 0; c < CPOL; c++) {
        float w1 = W1[(size_t)c*HID + o];
        float w2 = W1[(size_t)(c+256)*HID + o];
        #pragma unroll
        for (int p = 0; p < 16; p++) {
            float t = sT[p*CPOL + c];
            a1[p] += t*w1; a2[p] += t*w2;
        }
    }
    for (int p = 0; p < 16; p++)
        if (p0 + p < BOARD2) {
            g_P1[(p0+p)*HID + o] = a1[p];
            g_P2[(p0+p)*HID + o] = a2[p];
        }
}

// bias1 = b1 + pool @ W1[512:768]    (k-parallel)
__global__ void k_bias1(const float* __restrict__ W1, const float* __restrict__ b1) {
    __shared__ float red[8][32];
    int o  = blockIdx.x*32 + (threadIdx.x & 31);
    int kg = threadIdx.x >> 5;
    float s = 0.f;
    #pragma unroll 8
    for (int c = kg*32; c < kg*32 + 32; c++)
        s += g_pool[c] * W1[(size_t)(512+c)*HID + o];
    red[kg][threadIdx.x & 31] = s;
    __syncthreads();
    if (kg == 0) {
        float t = b1[o];
        #pragma unroll
        for (int j = 0; j < 8; j++) t += red[j][threadIdx.x & 31];
        g_bias1[o] = t;
    }
}

__global__ void k_cand_h(const float* __restrict__ cand) {
    int i = blockIdx.x*blockDim.x + threadIdx.x;
    if (i < NCAND*KCAND) g_candh[i] = __float2half_rn(cand[i]);
}

// W2^T -> fp16 [n][k]
__global__ void k_w2h(const float* __restrict__ W2) {
    __shared__ float t[32][33];
    int bx = blockIdx.x*32, by = blockIdx.y*32;   // bx: n base, by: k base
    int x = threadIdx.x, y = threadIdx.y;
    for (int i = y; i < 32; i += 8)
        t[i][x] = W2[(size_t)(by+i)*HID + bx + x];
    __syncthreads();
    for (int i = y; i < 32; i += 8)
        g_W2h[(size_t)(bx+i)*HID + by + x] = __float2half_rn(t[x][i]);
}

// W1c^T -> fp16 [n][64]
__global__ void k_w1ch(const float* __restrict__ W1) {
    int k = blockIdx.x;                    // 0..63
    int n = blockIdx.y*256 + threadIdx.x;  // 0..1023
    g_W1ch[(size_t)n*KCAND + k] = __float2half_rn(W1[(size_t)(768+k)*HID + n]);
}

__global__ void k_out_init(float* __restrict__ out, const float* __restrict__ b3) {
    int i = blockIdx.x*blockDim.x + threadIdx.x;
    if (i < NCAND) out[i] = b3[0];
}

// ---------------- main GEMM: 128x128 CTA, 4 warps of 64x64, fp16 HMMA + LDSM ----------------
// EPI==0: h1 = relu(cand@W1c + P1[go] + P2[to] + bias1)   (K=64)
// EPI==1: out += sum_n relu(h1@W2 + b2)[:,n] * W3[n]      (K=1024)
template<int EPI>
__global__ __launch_bounds__(THREADS, 2) void k_gemm(
    const float* __restrict__ b2, const float* __restrict__ W3, float* __restrict__ outp)
{
    extern __shared__ __align__(16) __half sm[];

    constexpr int lda = EPI ? HID : KCAND;
    constexpr int ldb = EPI ? HID : KCAND;
    constexpr int nck = EPI ? HID/BK : KCAND/BK;
    const __half* __restrict__ Ag = EPI ? g_h1  : g_candh;
    const __half* __restrict__ Bg = EPI ? g_W2h : g_W1ch;

    const int tid = threadIdx.x, lane = tid & 31, wid = tid >> 5;
    const int wm = wid >> 1, wn = wid & 1;       // 2x2 warp grid, 64x64 tiles
    const int g = lane >> 2, t4 = lane & 3;
    const int col0 = blockIdx.x * BN;            // x fastest -> A rows reused in L2
    const int row0 = blockIdx.y * BM;

    // ldmatrix lane-address components
    const int aRowL = lane & 15;                 // row within 16-row tile
    const int aKL   = (lane >> 4) << 3;          // +8 k for upper half lanes
    const int bNL   = (lane & 7) + ((lane >> 4) << 3);  // n row within 16-n tile
    const int bKL   = lane & 8;                  // +8 k for lanes 8-15/24-31

    auto issue = [&](int ck, int s) {
        __half* sA = sm + s*STAGE_HALVES;
        __half* sB = sA + SA_BUF;
        const int k0 = ck * BK;
        #pragma unroll
        for (int i = 0; i < 4; i++) {            // A: 128 rows x 32 halves
            int idx = tid + i*THREADS;
            int r = idx >> 2, c4 = idx & 3;
            cpa16(sA + r*SA_STRIDE + c4*8,
                  Ag + (size_t)(row0 + r)*lda + k0 + c4*8);
        }
        #pragma unroll
        for (int i = 0; i < 4; i++) {            // B: 128 n-rows x 32 halves
            int idx = tid + i*THREADS;
            int r = idx >> 2, c4 = idx & 3;
            cpa16(sB + r*SB_STRIDE + c4*8,
                  Bg + (size_t)(col0 + r)*ldb + k0 + c4*8);
        }
        CP_COMMIT();
    };

    float acc[4][8][4];
    #pragma unroll
    for (int mt = 0; mt < 4; mt++)
        #pragma unroll
        for (int nt = 0; nt < 8; nt++)
            #pragma unroll
            for (int q = 0; q < 4; q++) acc[mt][nt][q] = 0.f;

    #pragma unroll
    for (int s = 0; s < STAGES-1 && s < nck; s++) issue(s, s);

    for (int ck = 0; ck < nck; ck++) {
        const int buf = ck % STAGES;
        const int rem = nck - 1 - ck;
        if (ck + STAGES - 1 < nck) issue(ck + STAGES - 1, (ck + STAGES - 1) % STAGES);
        if (rem >= STAGES-1) cp_wait<STAGES-1>();
        else if (rem == 2)   cp_wait<2>();
        else if (rem == 1)   cp_wait<1>();
        else                 cp_wait<0>();
        __syncthreads();

        const __half* sA = sm + buf*STAGE_HALVES;
        const __half* sB = sA + SA_BUF;
        const __half* pA = sA + (wm*64 + aRowL)*SA_STRIDE + aKL;
        const __half* pB = sB + (wn*64 + bNL)*SB_STRIDE + bKL;

        #pragma unroll
        for (int ks = 0; ks < 2; ks++) {         // two k16 steps
            const int kofs = ks*16;
            unsigned a[4][4], b[8][2];
            #pragma unroll
            for (int mt = 0; mt < 4; mt++)
                ldsm4(a[mt][0], a[mt][1], a[mt][2], a[mt][3],
                      pA + mt*16*SA_STRIDE + kofs);
            #pragma unroll
            for (int np = 0; np < 4; np++)
                ldsm4(b[2*np][0], b[2*np][1], b[2*np+1][0], b[2*np+1][1],
                      pB + np*16*SB_STRIDE + kofs);
            #pragma unroll
            for (int mt = 0; mt < 4; mt++)
                #pragma unroll
                for (int nt = 0; nt < 8; nt++)
                    mma16(acc[mt][nt], a[mt], b[nt]);
        }
        __syncthreads();
    }

    // -------- epilogue (C frag: c0,c1 = row g cols 2t4,2t4+1; c2,c3 = row g+8) ----
    if (EPI == 0) {
        #pragma unroll
        for (int mt = 0; mt < 4; mt++) {
            const int r1 = row0 + wm*64 + mt*16 + g;
            const int r2 = r1 + 8;
            const int go1 = g_go[r1], to1 = g_to[r1];
            const int go2 = g_go[r2], to2 = g_to[r2];
            const float* P1a = g_P1 + (size_t)go1*HID;
            const float* P2a = g_P2 + (size_t)to1*HID;
            const float* P1b = g_P1 + (size_t)go2*HID;
            const float* P2b = g_P2 + (size_t)to2*HID;
            #pragma unroll
            for (int nt = 0; nt < 8; nt++) {
                const int c = col0 + wn*64 + nt*8 + 2*t4;
                float2 bs  = *(const float2*)&g_bias1[c];
                float2 p1a = *(const float2*)&P1a[c];
                float2 p2a = *(const float2*)&P2a[c];
                float2 p1b = *(const float2*)&P1b[c];
                float2 p2b = *(const float2*)&P2b[c];
                float v0 = fmaxf(acc[mt][nt][0] + p1a.x + p2a.x + bs.x, 0.f);
                float v1 = fmaxf(acc[mt][nt][1] + p1a.y + p2a.y + bs.y, 0.f);
                float v2 = fmaxf(acc[mt][nt][2] + p1b.x + p2b.x + bs.x, 0.f);
                float v3 = fmaxf(acc[mt][nt][3] + p1b.y + p2b.y + bs.y, 0.f);
                *(__half2*)&g_h1[(size_t)r1*HID + c] = __floats2half2_rn(v0, v1);
                *(__half2*)&g_h1[(size_t)r2*HID + c] = __floats2half2_rn(v2, v3);
            }
        }
    } else {
        float rs[4][2];
        #pragma unroll
        for (int mt = 0; mt < 4; mt++) { rs[mt][0] = 0.f; rs[mt][1] = 0.f; }
        #pragma unroll
        for (int nt = 0; nt < 8; nt++) {
            const int c = col0 + wn*64 + nt*8 + 2*t4;
            float2 bb = *(const float2*)&b2[c];
            float2 ww = *(const float2*)&W3[c];
            #pragma unroll
            for (int mt = 0; mt < 4; mt++) {
                rs[mt][0] += fmaxf(acc[mt][nt][0] + bb.x, 0.f)*ww.x
                           + fmaxf(acc[mt][nt][1] + bb.y, 0.f)*ww.y;
                rs[mt][1] += fmaxf(acc[mt][nt][2] + bb.x, 0.f)*ww.x
                           + fmaxf(acc[mt][nt][3] + bb.y, 0.f)*ww.y;
            }
        }
        #pragma unroll
        for (int mt = 0; mt < 4; mt++)
            #pragma unroll
            for (int j = 0; j < 2; j++) {
                float v = rs[mt][j];
                v += __shfl_xor_sync(0xffffffffu, v, 1);
                v += __shfl_xor_sync(0xffffffffu, v, 2);
                if (t4 == 0)
                    atomicAdd(outp + row0 + wm*64 + mt*16 + g + 8*j, v);
            }
    }
}

// ---------------- launch ----------------
extern "C" void kernel_launch(void* const* d_in, const int* in_sizes, int n_in,
                              void* d_out, int out_size)
{
    const float* pfm  = (const float*)d_in[0];
    const float* cand = (const float*)d_in[1];
    const float* W1   = (const float*)d_in[2];
    const float* b1   = (const float*)d_in[3];
    const float* W2   = (const float*)d_in[4];
    const float* b2   = (const float*)d_in[5];
    const float* W3   = (const float*)d_in[6];
    const float* b3   = (const float*)d_in[7];
    float* out = (float*)d_out;

    cudaFuncSetAttribute(k_gemm<0>, cudaFuncAttributeMaxDynamicSharedMemorySize, SMEM_BYTES);
    cudaFuncSetAttribute(k_gemm<1>, cudaFuncAttributeMaxDynamicSharedMemorySize, SMEM_BYTES);

    k_prep<<<CPOL, 128>>>(pfm);
    k_pos<<<NCAND/256, 256>>>(cand);
    k_pw<<<dim3(23, 8), 128>>>(W1);
    k_bias1<<<HID/32, 256>>>(W1, b1);
    k_cand_h<<<(NCAND*KCAND)/256, 256>>>(cand);
    k_w2h<<<dim3(HID/32, HID/32), dim3(32, 8)>>>(W2);
    k_w1ch<<<dim3(KCAND, HID/256), 256>>>(W1);
    k_out_init<<<NCAND/256, 256>>>(out, b3);

    dim3 grid(HID/BN, NCAND/BM);   // (8, 512): col-block fastest
    k_gemm<0><<<grid, THREADS, SMEM_BYTES>>>(nullptr, nullptr, nullptr);
    k_gemm<1><<<grid, THREADS, SMEM_BYTES>>>(b2, W3, out);
}